// round 8
// baseline (speedup 1.0000x reference)
#include <cuda_runtime.h>

// SGD_Hankel TT-chain: N=65536, L=128, D=4, R=8, O=2.  S=2 samples/thread.
// R8: R7 (92.6us) with two scheduling changes, zero structural changes:
//   - remove both __syncwarp()s at chunk boundaries (xbuf is warp-private;
//     per-warp shared-mem program order makes them redundant; they were
//     fencing the 16 STS.128 into a bubble)
//   - #pragma unroll 2 on the step loop so ptxas can hoist step s+1's core
//     LDS into step s's FMA tail

#define DV 4
#define RV 8
#define LV 128
#define NSTEP 126
#define HALF  63

typedef unsigned long long u64;

__device__ __forceinline__ u64 fpack(float a, float b) {
    u64 r; asm("mov.b64 %0, {%1,%2};" : "=l"(r) : "f"(a), "f"(b)); return r;
}
__device__ __forceinline__ u64 fdup(float a) {
    u64 r; asm("mov.b64 %0, {%1,%1};" : "=l"(r) : "f"(a)); return r;
}
__device__ __forceinline__ void funpack(u64 v, float& a, float& b) {
    asm("mov.b64 {%0,%1}, %2;" : "=f"(a), "=f"(b) : "l"(v));
}
__device__ __forceinline__ u64 f2mul(u64 a, u64 b) {
    u64 d; asm("mul.rn.f32x2 %0, %1, %2;" : "=l"(d) : "l"(a), "l"(b)); return d;
}
__device__ __forceinline__ u64 f2fma(u64 a, u64 b, u64 c) {
    u64 d; asm("fma.rn.f32x2 %0, %1, %2, %3;" : "=l"(d) : "l"(a), "l"(b), "l"(c)); return d;
}

// smem: phased cores [63][3][8][8] + xbuf 4 warps * 2048 words + first/last
#define SCORE_FLOATS (HALF * 3 * RV * RV)      // 12096
#define XBUF_FLOATS  (4 * 2048)                // 8192
#define SFL_OFF      (SCORE_FLOATS + XBUF_FLOATS)
#define SMEM_FLOATS  (SFL_OFF + 96)
#define SMEM_BYTES   (SMEM_FLOATS * 4)         // 81536

// Issue the 16 coalesced LDG.128 for chunk c into the register buffer.
// (N is an exact multiple of 256 -> no guards.)
__device__ __forceinline__ void ldg_chunk(float4 (&pv)[16], const float* __restrict__ x,
                                          int base_w, int lane, int c)
{
    const int s8 = lane & 7;
    const int g  = lane >> 3;
    #pragma unroll
    for (int it = 0; it < 16; ++it) {
        int r = g + it * 4;                           // local row 0..63
        int n = base_w + ((r & 32) ? (r - 32 + 128) : r);
        pv[it] = *(const float4*)(x + (size_t)n * (LV * DV) + (c * 8 + s8) * 4);
    }
}

// Publish the prefetched chunk: 16 STS.128, swizzled pos=(r+s8)&63.
// xbuf layout: [s8][pos] float4.
__device__ __forceinline__ void sts_chunk(const float4 (&pv)[16], float* xw, int lane)
{
    const int s8 = lane & 7;
    const int g  = lane >> 3;
    #pragma unroll
    for (int it = 0; it < 16; ++it) {
        int r = g + it * 4;
        int pos = (r + s8) & 63;
        *(float4*)(xw + (s8 * 64 + pos) * 4) = pv[it];
    }
}

extern "C" __global__ void __launch_bounds__(128, 2)
tt_chain_kernel(const float* __restrict__ x,
                const float* __restrict__ core_first,
                const float* __restrict__ cores_mid,
                const float* __restrict__ core_last,
                float* __restrict__ out,
                int n_total)
{
    extern __shared__ float sm[];
    float* score  = sm;                    // [63][3][8][8]
    float* xbuf   = sm + SCORE_FLOATS;
    float* sfirst = sm + SFL_OFF;          // 32 floats [j][k]
    float* slast  = sfirst + 32;           // 64 floats [k][j][l]

    const int tid  = threadIdx.x;
    const int lane = tid & 31;
    const int w    = tid >> 5;
    float* xw = xbuf + w * 2048;

    const int n0 = blockIdx.x * 256 + tid;
    const int n1 = n0 + 128;
    const int base_w = blockIdx.x * 256 + w * 32;

    float4 pv[16];
    // Prefetch chunk 0 immediately (overlaps core staging + barriers).
    ldg_chunk(pv, x, base_w, lane, 0);

    if (tid < 32)            sfirst[tid] = core_first[tid];
    else if (tid < 96)       slast[tid - 32] = core_last[tid - 32];

    u64 mpA[4], mpB[4];

    #pragma unroll 1
    for (int phase = 0; phase < 2; ++phase) {
        __syncthreads();    // prior-phase consumers done before core overwrite
        // stage cores for this phase: [s][k][j][l] -> [s][j][k][l], j<3
        for (int u = tid; u < HALF * 48; u += 128) {
            int st = u / 48;
            int rr = u - st * 48;
            int j = rr >> 4, k = (rr >> 1) & 7, h = rr & 1;
            float4 v = *(const float4*)(cores_mid
                        + (((size_t)(phase * HALF + st) * RV + k) * DV + j) * RV + h * 4);
            *(float4*)(score + ((st * 3 + j) * RV + k) * RV + h * 4) = v;
        }
        __syncthreads();

        if (phase == 0) {
            // publish chunk 0, start prefetch of chunk 1, init merged from l=0
            sts_chunk(pv, xw, lane);
            ldg_chunk(pv, x, base_w, lane, 1);

            // l=0: s8=0 -> pos = row
            float4 xa = *(const float4*)(xw + lane * 4);
            float4 xb = *(const float4*)(xw + (32 + lane) * 4);
            float mA[8], mB[8];
            #pragma unroll
            for (int k = 0; k < 8; ++k) {
                mA[k] = sfirst[k] * xa.x + sfirst[8 + k] * xa.y
                      + sfirst[16 + k] * xa.z + sfirst[24 + k] * xa.w;
                mB[k] = sfirst[k] * xb.x + sfirst[8 + k] * xb.y
                      + sfirst[16 + k] * xb.z + sfirst[24 + k] * xb.w;
            }
            #pragma unroll
            for (int p = 0; p < 4; ++p) {
                mpA[p] = fpack(mA[2 * p], mA[2 * p + 1]);
                mpB[p] = fpack(mB[2 * p], mB[2 * p + 1]);
            }
        }

        const float* cp = score;
        #pragma unroll 2
        for (int sc = 0; sc < HALF; ++sc) {
            const int l = phase * HALF + sc + 1;       // x index consumed this step
            if ((l & 7) == 0) {
                // pv holds chunk c=l>>3 (LDG'd 8 steps ago -> data long arrived).
                // xbuf is warp-private: per-warp shared-mem program order makes
                // this safe without __syncwarp.
                sts_chunk(pv, xw, lane);
                const int c = l >> 3;
                if (c < 15) ldg_chunk(pv, x, base_w, lane, c + 1);
            }
            const int s8 = l & 7;

            // x reads: one LDS.128 per sample (issue early to hide latency)
            float4 xa = *(const float4*)(xw + (s8 * 64 + ((lane + s8) & 63)) * 4);
            float4 xb = *(const float4*)(xw + (s8 * 64 + ((lane + 32 + s8) & 63)) * 4);

            // duplicate merged scalars into packed lanes
            u64 mdA[8], mdB[8];
            #pragma unroll
            for (int p = 0; p < 4; ++p) {
                float a0, a1, b0, b1;
                funpack(mpA[p], a0, a1);
                funpack(mpB[p], b0, b1);
                mdA[2 * p] = fdup(a0); mdA[2 * p + 1] = fdup(a1);
                mdB[2 * p] = fdup(b0); mdB[2 * p + 1] = fdup(b1);
            }

            u64 Ya[3][4], Yb[3][4];
            #pragma unroll
            for (int j = 0; j < 3; ++j) {
                const float* cj = cp + j * 64;
                #pragma unroll
                for (int k = 0; k < 8; ++k) {
                    ulonglong2 cA = *(const ulonglong2*)(cj + k * 8);
                    ulonglong2 cB = *(const ulonglong2*)(cj + k * 8 + 4);
                    if (k == 0) {
                        Ya[j][0] = f2mul(mdA[0], cA.x); Ya[j][1] = f2mul(mdA[0], cA.y);
                        Ya[j][2] = f2mul(mdA[0], cB.x); Ya[j][3] = f2mul(mdA[0], cB.y);
                        Yb[j][0] = f2mul(mdB[0], cA.x); Yb[j][1] = f2mul(mdB[0], cA.y);
                        Yb[j][2] = f2mul(mdB[0], cB.x); Yb[j][3] = f2mul(mdB[0], cB.y);
                    } else {
                        Ya[j][0] = f2fma(mdA[k], cA.x, Ya[j][0]);
                        Ya[j][1] = f2fma(mdA[k], cA.y, Ya[j][1]);
                        Ya[j][2] = f2fma(mdA[k], cB.x, Ya[j][2]);
                        Ya[j][3] = f2fma(mdA[k], cB.y, Ya[j][3]);
                        Yb[j][0] = f2fma(mdB[k], cA.x, Yb[j][0]);
                        Yb[j][1] = f2fma(mdB[k], cA.y, Yb[j][1]);
                        Yb[j][2] = f2fma(mdB[k], cB.x, Yb[j][2]);
                        Yb[j][3] = f2fma(mdB[k], cB.y, Yb[j][3]);
                    }
                }
            }

            // identity slice: j=3 term is x3 * merged (exact)
            const u64 a0 = fdup(xa.x), a1 = fdup(xa.y), a2 = fdup(xa.z), a3 = fdup(xa.w);
            const u64 b0 = fdup(xb.x), b1 = fdup(xb.y), b2 = fdup(xb.z), b3 = fdup(xb.w);
            #pragma unroll
            for (int p = 0; p < 4; ++p) {
                mpA[p] = f2fma(a3, mpA[p],
                         f2fma(a2, Ya[2][p],
                         f2fma(a1, Ya[1][p],
                         f2mul(a0, Ya[0][p]))));
                mpB[p] = f2fma(b3, mpB[p],
                         f2fma(b2, Yb[2][p],
                         f2fma(b1, Yb[1][p],
                         f2mul(b0, Yb[0][p]))));
            }
            cp += 3 * 64;
        }
    }

    // ---- final contraction with core_last: out[l] = sum_j x_j (sum_k m_k C[k][j][l]) ----
    {
        const int s8 = 127 & 7;                // 7, chunk 15 already staged
        float4 xa = *(const float4*)(xw + (s8 * 64 + ((lane + s8) & 63)) * 4);
        float4 xb = *(const float4*)(xw + (s8 * 64 + ((lane + 32 + s8) & 63)) * 4);

        u64 mdA[8], mdB[8];
        #pragma unroll
        for (int p = 0; p < 4; ++p) {
            float a0, a1, b0, b1;
            funpack(mpA[p], a0, a1);
            funpack(mpB[p], b0, b1);
            mdA[2 * p] = fdup(a0); mdA[2 * p + 1] = fdup(a1);
            mdB[2 * p] = fdup(b0); mdB[2 * p + 1] = fdup(b1);
        }
        u64 YlA[4], YlB[4];
        #pragma unroll
        for (int j = 0; j < 4; ++j) {
            u64 accA = f2mul(mdA[0], *(const u64*)(slast + j * 2));
            u64 accB = f2mul(mdB[0], *(const u64*)(slast + j * 2));
            #pragma unroll
            for (int k = 1; k < 8; ++k) {
                u64 cv = *(const u64*)(slast + (k * DV + j) * 2);
                accA = f2fma(mdA[k], cv, accA);
                accB = f2fma(mdB[k], cv, accB);
            }
            YlA[j] = accA; YlB[j] = accB;
        }
        u64 oA = f2fma(fdup(xa.w), YlA[3],
                 f2fma(fdup(xa.z), YlA[2],
                 f2fma(fdup(xa.y), YlA[1],
                 f2mul(fdup(xa.x), YlA[0]))));
        u64 oB = f2fma(fdup(xb.w), YlB[3],
                 f2fma(fdup(xb.z), YlB[2],
                 f2fma(fdup(xb.y), YlB[1],
                 f2mul(fdup(xb.x), YlB[0]))));
        float r0, r1;
        if (n0 < n_total) {
            funpack(oA, r0, r1);
            float2 res; res.x = r0; res.y = r1;
            *(float2*)(out + 2 * (size_t)n0) = res;
        }
        if (n1 < n_total) {
            funpack(oB, r0, r1);
            float2 res; res.x = r0; res.y = r1;
            *(float2*)(out + 2 * (size_t)n1) = res;
        }
    }
}

extern "C" void kernel_launch(void* const* d_in, const int* in_sizes, int n_in,
                              void* d_out, int out_size)
{
    const float* x  = (const float*)d_in[0];
    const float* cf = (const float*)d_in[1];
    const float* cm = (const float*)d_in[2];
    const float* cl = (const float*)d_in[3];
    float* out = (float*)d_out;

    const int n_total = in_sizes[0] / (LV * DV);   // 65536

    cudaFuncSetAttribute(tt_chain_kernel,
                         cudaFuncAttributeMaxDynamicSharedMemorySize, SMEM_BYTES);

    const int threads = 128;
    const int blocks = (n_total + 255) / 256;      // 2 samples per thread
    tt_chain_kernel<<<blocks, threads, SMEM_BYTES>>>(x, cf, cm, cl, out, n_total);
}